// round 17
// baseline (speedup 1.0000x reference)
#include <cuda_runtime.h>

#define H_IMG 512
#define W_IMG 512
#define NMAX  2048
#define TILE  16
#define TX_N  (W_IMG / TILE)   /* 32 */
#define TY_N  (H_IMG / TILE)   /* 32 */
#define NTILES (TX_N * TY_N)   /* 1024 */
#define CHUNK 256              /* gaussians per staged chunk */
#define PAIRS (CHUNK / 2)      /* 128 packed pairs */

#define TWO_PI_F        6.28318530717958647692f
#define LOG2E_F         1.44269504088896340736f
#define LOG2_ALPHA_MIN  -7.99435344f    /* log2(1/255) */
#define E_CAP           254.745f        /* 0.999 * 255 */
#define FEAT_SCALE      0.003921568859f /* 1/255 */
#define NEG_BIG         -126.0f
#define L_DUMMY         -1.0e4f

typedef unsigned long long u64;

#define PACKF2(d, lo, hi)  asm("mov.b64 %0, {%1,%2};" : "=l"(d) : "f"(lo), "f"(hi))
#define UNPACKF2(lo, hi, s) asm("mov.b64 {%0,%1}, %2;" : "=f"(lo), "=f"(hi) : "l"(s))
#define FMA2(d, a, b, c)   asm("fma.rn.f32x2 %0, %1, %2, %3;" : "=l"(d) : "l"(a), "l"(b), "l"(c))
#define MUL2(d, a, b)      asm("mul.rn.f32x2 %0, %1, %2;" : "=l"(d) : "l"(a), "l"(b))
#define ADD2(d, a, b)      asm("add.rn.f32x2 %0, %1, %2;" : "=l"(d) : "l"(a), "l"(b))
#define SLCT(d, a, b, c)   asm("slct.f32.f32 %0, %1, %2, %3;" : "=f"(d) : "f"(a), "f"(b), "f"(c))
#define EX2(d, a)          asm("ex2.approx.ftz.f32 %0, %1;" : "=f"(d) : "f"(a))

// Per-gaussian precomputed parameters (pre-scaled)
__device__ float4 g_P0[NMAX];   // mx, my, A'(=-0.5*log2e*c0), B'(=-0.5*log2e*c2)
__device__ float4 g_P1[NMAX];   // C'(=-log2e*c1), L'(=log2(op)-LOG2_ALPHA_MIN), fr', fg'
__device__ float  g_FB[NMAX];   // fb'
// Per-tile gaussian index lists
__device__ int    g_tile_cnt[NTILES];          // zero at load; render re-zeroes
__device__ int    g_tile_list[NTILES][NMAX];   // 8 MB static scratch

// One WARP per gaussian; fast-math; tight per-axis AABB; exact ellipse-vs-box
// cull per candidate tile. PDL completion trigger at the end.
__global__ __launch_bounds__(256)
void prep_bin_kernel(const float* __restrict__ xyz,
                     const float* __restrict__ scaling,
                     const float* __restrict__ rot,
                     const float* __restrict__ feat,
                     const float* __restrict__ opac,
                     int N)
{
    int warp = (blockIdx.x * blockDim.x + threadIdx.x) >> 5;
    int lane = threadIdx.x & 31;
    int i = warp;
    if (i < N) {
        float theta = (1.0f / (1.0f + __expf(-rot[i]))) * TWO_PI_F;
        float s0 = fabsf(scaling[2*i + 0]); s0 *= s0;
        float s1 = fabsf(scaling[2*i + 1]); s1 *= s1;
        float cs = __cosf(theta);
        float sn = __sinf(theta);

        float a = cs*cs*s0 + sn*sn*s1;     // Sigma_xx
        float b = cs*sn*(s0 - s1);         // Sigma_xy
        float c = sn*sn*s0 + cs*cs*s1;     // Sigma_yy
        float inv_det = 1.0f / (a*c - b*b);
        float c0 =  c * inv_det;
        float c1 = -b * inv_det;
        float c2 =  a * inv_det;

        float mx = 0.5f * ((xyz[2*i + 0] + 1.0f) * (float)W_IMG - 1.0f);
        float my = 0.5f * ((xyz[2*i + 1] + 1.0f) * (float)H_IMG - 1.0f);

        float op = opac[i];
        if (lane == 0) {
            g_P0[i] = make_float4(mx, my, -0.5f * LOG2E_F * c0, -0.5f * LOG2E_F * c2);
            g_P1[i] = make_float4(-LOG2E_F * c1, __log2f(op) - LOG2_ALPHA_MIN,
                                  feat[3*i + 0] * FEAT_SCALE, feat[3*i + 1] * FEAT_SCALE);
            g_FB[i] = feat[3*i + 2] * FEAT_SCALE;
        }

        float lnthr = __logf(op * 255.0f);    // contributes iff sigma <= lnthr
        if (lnthr > 0.0f) {
            float thr = lnthr + 1e-2f;        // margin >> fp noise

            float aq = 0.5f * c0;
            float bq = c1;
            float cq = 0.5f * c2;
            float inv2aq = 0.5f / aq;
            float inv2cq = 0.5f / cq;

            float rx = sqrtf(2.0f * thr * a);
            float ry = sqrtf(2.0f * thr * c);

            int tx_lo = max(0,        (int)floorf((mx - rx) * (1.0f / TILE)));
            int tx_hi = min(TX_N - 1, (int)floorf((mx + rx) * (1.0f / TILE)));
            int ty_lo = max(0,        (int)floorf((my - ry) * (1.0f / TILE)));
            int ty_hi = min(TY_N - 1, (int)floorf((my + ry) * (1.0f / TILE)));

            if (tx_hi >= tx_lo && ty_hi >= ty_lo) {
                int w = tx_hi - tx_lo + 1;
                int cand = w * (ty_hi - ty_lo + 1);

                for (int sidx = lane; sidx < cand; sidx += 32) {
                    int tx = tx_lo + (sidx % w);
                    int ty = ty_lo + (sidx / w);
                    float lx = (float)(tx * TILE) - mx;
                    float hx = lx + (float)(TILE - 1);
                    float ly = (float)(ty * TILE) - my;
                    float hy = ly + (float)(TILE - 1);

                    float smin;
                    if (lx <= 0.0f && hx >= 0.0f && ly <= 0.0f && hy >= 0.0f) {
                        smin = 0.0f;
                    } else {
                        float dyc = fminf(fmaxf(-bq * lx * inv2cq, ly), hy);
                        float e0 = fmaf(cq * dyc, dyc, fmaf(bq * lx, dyc, aq * lx * lx));
                        dyc = fminf(fmaxf(-bq * hx * inv2cq, ly), hy);
                        float e1 = fmaf(cq * dyc, dyc, fmaf(bq * hx, dyc, aq * hx * hx));
                        float dxc = fminf(fmaxf(-bq * ly * inv2aq, lx), hx);
                        float e2 = fmaf(aq * dxc, dxc, fmaf(bq * ly, dxc, cq * ly * ly));
                        dxc = fminf(fmaxf(-bq * hy * inv2aq, lx), hx);
                        float e3 = fmaf(aq * dxc, dxc, fmaf(bq * hy, dxc, cq * hy * hy));
                        smin = fminf(fminf(e0, e1), fminf(e2, e3));
                    }

                    if (smin <= thr) {
                        int t = ty * TX_N + tx;
                        int pos = atomicAdd(&g_tile_cnt[t], 1);
                        g_tile_list[t][pos] = i;
                    }
                }
            }
        }
    }

#if __CUDA_ARCH__ >= 900
    cudaTriggerProgrammaticLaunchCompletion();
#endif
}

// 64 threads/CTA, 2x2 quad per thread. Gaussians processed in PACKED PAIRS:
// all sigma math and accumulation use f32x2 (FFMA2) — lo component = even
// gaussian, hi = odd. Params staged into shared PRE-PACKED (mx/my negated so
// the loop uses packed ADD). slct->-126 + ex2.ftz zeroes sub-threshold alpha.
__global__ __launch_bounds__(64, 8)
void render_kernel(float* __restrict__ out)
{
    __shared__ u64 sNMX[PAIRS];   // (-mx0, -mx1)
    __shared__ u64 sNMY[PAIRS];
    __shared__ u64 sA[PAIRS];
    __shared__ u64 sB[PAIRS];
    __shared__ u64 sC[PAIRS];
    __shared__ u64 sL[PAIRS];
    __shared__ u64 sFR[PAIRS];
    __shared__ u64 sFG[PAIRS];
    __shared__ u64 sFB2[PAIRS];

    const int tid = threadIdx.x;
    const int tx  = tid & 7;
    const int ty  = tid >> 3;

    const int tile = blockIdx.y * TX_N + blockIdx.x;
    const int px0 = blockIdx.x * TILE + tx;
    const int py0 = blockIdx.y * TILE + ty;
    const float fx0 = (float)px0;
    const float fy0 = (float)py0;

#if __CUDA_ARCH__ >= 900
    cudaGridDependencySynchronize();
#endif

    const int cnt = g_tile_cnt[tile];

    u64 fx0d, fy0d, c8d;
    PACKF2(fx0d, fx0, fx0);
    PACKF2(fy0d, fy0, fy0);
    PACKF2(c8d, 8.0f, 8.0f);

    // packed accumulators: lo = even-gaussian partial, hi = odd
    u64 A00r = 0, A00g = 0, A00b = 0;
    u64 A10r = 0, A10g = 0, A10b = 0;
    u64 A01r = 0, A01g = 0, A01b = 0;
    u64 A11r = 0, A11g = 0, A11b = 0;

    for (int base = 0; base < cnt; base += CHUNK) {
        int m = cnt - base;
        if (m > CHUNK) m = CHUNK;
        int mp = (m + 1) >> 1;

        // stage pre-packed pairs (2 pairs per thread)
        for (int p = tid; p < mp; p += 64) {
            int k0 = 2 * p, k1 = k0 + 1;
            int gi0 = g_tile_list[tile][base + k0];
            int gi1 = (k1 < m) ? g_tile_list[tile][base + k1] : gi0;
            float4 a0 = g_P0[gi0], a1 = g_P0[gi1];
            float4 b0 = g_P1[gi0], b1 = g_P1[gi1];
            float  f0 = g_FB[gi0], f1 = g_FB[gi1];
            float  L1v = (k1 < m) ? b1.y : L_DUMMY;   // dummy hi contributes ~0

            u64 t;
            PACKF2(t, -a0.x, -a1.x); sNMX[p] = t;
            PACKF2(t, -a0.y, -a1.y); sNMY[p] = t;
            PACKF2(t,  a0.z,  a1.z); sA[p]   = t;
            PACKF2(t,  a0.w,  a1.w); sB[p]   = t;
            PACKF2(t,  b0.x,  b1.x); sC[p]   = t;
            PACKF2(t,  b0.y,  L1v ); sL[p]   = t;
            PACKF2(t,  b0.z,  b1.z); sFR[p]  = t;
            PACKF2(t,  b0.w,  b1.w); sFG[p]  = t;
            PACKF2(t,  f0,    f1  ); sFB2[p] = t;
        }
        __syncthreads();

        #pragma unroll 2
        for (int p = 0; p < mp; ++p) {
            u64 nmx = sNMX[p], nmy = sNMY[p];
            u64 Ap = sA[p], Bp = sB[p], Cp = sC[p], Lp = sL[p];
            u64 FRp = sFR[p], FGp = sFG[p], FBp = sFB2[p];

            u64 dx0p, dx1p, dy0p, dy1p;
            ADD2(dx0p, fx0d, nmx);
            ADD2(dx1p, dx0p, c8d);
            ADD2(dy0p, fy0d, nmy);
            ADD2(dy1p, dy0p, c8d);

            u64 adx0, adx1, bd0, bd1, rt0, rt1;
            MUL2(adx0, Ap, dx0p);
            MUL2(adx1, Ap, dx1p);
            MUL2(bd0, Bp, dy0p);
            MUL2(bd1, Bp, dy1p);
            FMA2(rt0, bd0, dy0p, Lp);   // B'*dy0^2 + L'
            FMA2(rt1, bd1, dy1p, Lp);

            u64 t00, t10, t01, t11;
            FMA2(t00, Cp, dy0p, adx0);
            FMA2(t10, Cp, dy0p, adx1);
            FMA2(t01, Cp, dy1p, adx0);
            FMA2(t11, Cp, dy1p, adx1);

            u64 b00p, b10p, b01p, b11p;
            FMA2(b00p, t00, dx0p, rt0);
            FMA2(b10p, t10, dx1p, rt0);
            FMA2(b01p, t01, dx0p, rt1);
            FMA2(b11p, t11, dx1p, rt1);

            // scalar halves: slct->-126 when arg<0, ex2, cap
            float bl, bh, zl, zh, el, eh;
            u64 e00p, e10p, e01p, e11p;

            UNPACKF2(bl, bh, b00p);
            SLCT(zl, bl, NEG_BIG, bl); SLCT(zh, bh, NEG_BIG, bh);
            EX2(el, zl); EX2(eh, zh);
            el = fminf(el, E_CAP); eh = fminf(eh, E_CAP);
            PACKF2(e00p, el, eh);

            UNPACKF2(bl, bh, b10p);
            SLCT(zl, bl, NEG_BIG, bl); SLCT(zh, bh, NEG_BIG, bh);
            EX2(el, zl); EX2(eh, zh);
            el = fminf(el, E_CAP); eh = fminf(eh, E_CAP);
            PACKF2(e10p, el, eh);

            UNPACKF2(bl, bh, b01p);
            SLCT(zl, bl, NEG_BIG, bl); SLCT(zh, bh, NEG_BIG, bh);
            EX2(el, zl); EX2(eh, zh);
            el = fminf(el, E_CAP); eh = fminf(eh, E_CAP);
            PACKF2(e01p, el, eh);

            UNPACKF2(bl, bh, b11p);
            SLCT(zl, bl, NEG_BIG, bl); SLCT(zh, bh, NEG_BIG, bh);
            EX2(el, zl); EX2(eh, zh);
            el = fminf(el, E_CAP); eh = fminf(eh, E_CAP);
            PACKF2(e11p, el, eh);

            // packed accumulation (12 FFMA2 replace 24 FFMA)
            FMA2(A00r, e00p, FRp, A00r);
            FMA2(A00g, e00p, FGp, A00g);
            FMA2(A00b, e00p, FBp, A00b);
            FMA2(A10r, e10p, FRp, A10r);
            FMA2(A10g, e10p, FGp, A10g);
            FMA2(A10b, e10p, FBp, A10b);
            FMA2(A01r, e01p, FRp, A01r);
            FMA2(A01g, e01p, FGp, A01g);
            FMA2(A01b, e01p, FBp, A01b);
            FMA2(A11r, e11p, FRp, A11r);
            FMA2(A11g, e11p, FGp, A11g);
            FMA2(A11b, e11p, FBp, A11b);
        }
        __syncthreads();
    }

    if (tid == 0) g_tile_cnt[tile] = 0;   // leave zeroed for next launch

    // horizontal fold (even-partial + odd-partial), clamp, store
    float lo, hi;
    float a00r, a00g, a00b, a10r, a10g, a10b, a01r, a01g, a01b, a11r, a11g, a11b;
    UNPACKF2(lo, hi, A00r); a00r = lo + hi;
    UNPACKF2(lo, hi, A00g); a00g = lo + hi;
    UNPACKF2(lo, hi, A00b); a00b = lo + hi;
    UNPACKF2(lo, hi, A10r); a10r = lo + hi;
    UNPACKF2(lo, hi, A10g); a10g = lo + hi;
    UNPACKF2(lo, hi, A10b); a10b = lo + hi;
    UNPACKF2(lo, hi, A01r); a01r = lo + hi;
    UNPACKF2(lo, hi, A01g); a01g = lo + hi;
    UNPACKF2(lo, hi, A01b); a01b = lo + hi;
    UNPACKF2(lo, hi, A11r); a11r = lo + hi;
    UNPACKF2(lo, hi, A11g); a11g = lo + hi;
    UNPACKF2(lo, hi, A11b); a11b = lo + hi;

    const int px1 = px0 + 8;
    const int py1 = py0 + 8;
    // out layout: [1, 3, H, W]
    out[(0 * H_IMG + py0) * W_IMG + px0] = fminf(fmaxf(a00r, 0.0f), 1.0f);
    out[(0 * H_IMG + py0) * W_IMG + px1] = fminf(fmaxf(a10r, 0.0f), 1.0f);
    out[(0 * H_IMG + py1) * W_IMG + px0] = fminf(fmaxf(a01r, 0.0f), 1.0f);
    out[(0 * H_IMG + py1) * W_IMG + px1] = fminf(fmaxf(a11r, 0.0f), 1.0f);
    out[(1 * H_IMG + py0) * W_IMG + px0] = fminf(fmaxf(a00g, 0.0f), 1.0f);
    out[(1 * H_IMG + py0) * W_IMG + px1] = fminf(fmaxf(a10g, 0.0f), 1.0f);
    out[(1 * H_IMG + py1) * W_IMG + px0] = fminf(fmaxf(a01g, 0.0f), 1.0f);
    out[(1 * H_IMG + py1) * W_IMG + px1] = fminf(fmaxf(a11g, 0.0f), 1.0f);
    out[(2 * H_IMG + py0) * W_IMG + px0] = fminf(fmaxf(a00b, 0.0f), 1.0f);
    out[(2 * H_IMG + py0) * W_IMG + px1] = fminf(fmaxf(a10b, 0.0f), 1.0f);
    out[(2 * H_IMG + py1) * W_IMG + px0] = fminf(fmaxf(a01b, 0.0f), 1.0f);
    out[(2 * H_IMG + py1) * W_IMG + px1] = fminf(fmaxf(a11b, 0.0f), 1.0f);
}

extern "C" void kernel_launch(void* const* d_in, const int* in_sizes, int n_in,
                              void* d_out, int out_size)
{
    const float* xyz     = (const float*)d_in[0];
    const float* scaling = (const float*)d_in[1];
    const float* rot     = (const float*)d_in[2];
    const float* feat    = (const float*)d_in[3];
    const float* opac    = (const float*)d_in[4];
    float* out = (float*)d_out;

    int N = in_sizes[0] / 2;
    if (N > NMAX) N = NMAX;

    // primary: one warp per gaussian
    prep_bin_kernel<<<(N * 32 + 255) / 256, 256>>>(xyz, scaling, rot, feat, opac, N);

    // secondary via PDL
    cudaLaunchConfig_t cfg = {};
    cfg.gridDim  = dim3(TX_N, TY_N, 1);
    cfg.blockDim = dim3(64, 1, 1);
    cfg.dynamicSmemBytes = 0;
    cudaLaunchAttribute attrs[1];
    attrs[0].id = cudaLaunchAttributeProgrammaticStreamSerialization;
    attrs[0].val.programmaticStreamSerializationAllowed = 1;
    cfg.attrs = attrs;
    cfg.numAttrs = 1;
    cudaLaunchKernelEx(&cfg, render_kernel, out);
}